// round 10
// baseline (speedup 1.0000x reference)
#include <cuda_runtime.h>
#include <cuda_bf16.h>
#include <stdint.h>

// ---------------- problem constants ----------------
#define NB   64
#define CH   256
#define HH   28
#define WW   28
#define HPX  900              // 30*30 padded pixels per image
#define NPIX (NB*HPX)         // 57600
#define NPIX_PAD 57728        // slack for tap offsets on garbage rows
#define MT   128              // pixels (M) per CTA
#define NMT  (NPIX/MT)        // 450
#define NSTAGE 36             // 9 taps * 4 ic-chunks (64 ic each)
#define NBUF 3
#define A_BYTES 16384         // 128 rows * 128B
#define B_BYTES 16384
#define STAGE_BYTES (A_BYTES + B_BYTES)        // 32768
#define SMEM_TOTAL (NBUF*STAGE_BYTES)          // 98304 -> 2 CTAs/SM

// ---------------- device scratch (no cudaMalloc allowed) ----------------
__device__ __align__(16) __nv_bfloat16 g_axs [(size_t)NPIX_PAD*CH];  // x - z_x, pad 0
__device__ __align__(16) __nv_bfloat16 g_amid[(size_t)NPIX_PAD*CH];  // mid - z_c1, pad 0
__device__ __align__(16) __nv_bfloat16 g_wb1[9*CH*CH];               // [tap][oc][ic]
__device__ __align__(16) __nv_bfloat16 g_wb2[9*CH*CH];

// ---------------- PTX helpers ----------------
__device__ __forceinline__ uint32_t smem_u32(const void* p) {
    uint32_t a;
    asm("{ .reg .u64 t; cvta.to.shared.u64 t, %1; cvt.u32.u64 %0, t; }" : "=r"(a) : "l"(p));
    return a;
}
__device__ __forceinline__ void cp16(uint32_t sdst, const void* gsrc) {
    asm volatile("cp.async.cg.shared.global [%0], [%1], 16;" :: "r"(sdst), "l"(gsrc));
}
#define CP_COMMIT() asm volatile("cp.async.commit_group;" ::: "memory")
template <int N> __device__ __forceinline__ void cp_wait() {
    asm volatile("cp.async.wait_group %0;" :: "n"(N) : "memory");
}
__device__ __forceinline__ void ldm4(uint32_t* r, uint32_t addr) {
    asm volatile("ldmatrix.sync.aligned.m8n8.x4.shared.b16 {%0,%1,%2,%3}, [%4];"
        : "=r"(r[0]), "=r"(r[1]), "=r"(r[2]), "=r"(r[3]) : "r"(addr));
}
__device__ __forceinline__ void mma_bf16(float* d, const uint32_t* a, const uint32_t* b) {
    asm volatile("mma.sync.aligned.m16n8k16.row.col.f32.bf16.bf16.f32 "
        "{%0,%1,%2,%3},{%4,%5,%6,%7},{%8,%9},{%0,%1,%2,%3};"
        : "+f"(d[0]), "+f"(d[1]), "+f"(d[2]), "+f"(d[3])
        : "r"(a[0]), "r"(a[1]), "r"(a[2]), "r"(a[3]), "r"(b[0]), "r"(b[1]));
}

// ---------------- packing kernels ----------------
#define RING_SLOTS (64*116 + 128)
__global__ void k_zero_halo() {
    int idx = blockIdx.x * blockDim.x + threadIdx.x;
    int total = RING_SLOTS * 32;
    if (idx >= 2 * total) return;
    int arr = idx >= total;
    int t = arr ? idx - total : idx;
    int chunk = t & 31;
    int slot  = t >> 5;
    size_t P;
    if (slot < 64 * 116) {
        int img = slot / 116, i = slot % 116;
        int q;
        if (i < 30)       q = i;
        else if (i < 60)  q = 870 + (i - 30);
        else if (i < 88)  q = (i - 60 + 1) * 30;
        else              q = (i - 88 + 1) * 30 + 29;
        P = (size_t)img * HPX + q;
    } else {
        P = (size_t)NPIX + (slot - 64 * 116);
    }
    int4 z = make_int4(0, 0, 0, 0);
    if (arr == 0) ((int4*)(g_axs  + P * 256))[chunk] = z;
    else          ((int4*)(g_amid + P * 256))[chunk] = z;
}

__global__ void k_pack_x(const float* __restrict__ x, const float* __restrict__ pzx) {
    __shared__ __nv_bfloat16 s[28 * 258];
    int n  = blockIdx.x / 28;
    int oh = blockIdx.x % 28;
    float zx = *pzx;
    for (int i = threadIdx.x; i < 28 * 256; i += 256) {
        int c = i / 28, ow = i % 28;
        float g = x[(((size_t)n * CH + c) * HH + oh) * WW + ow];
        s[ow * 258 + c] = __float2bfloat16(__fsub_rn(g, zx));
    }
    __syncthreads();
    for (int i = threadIdx.x; i < 28 * 256; i += 256) {
        int ow = i >> 8, c = i & 255;
        g_axs[((size_t)n * HPX + (oh + 1) * 30 + ow + 1) * CH + c] = s[ow * 258 + c];
    }
}

__global__ void k_pack_w2(const float* __restrict__ w1, const float* __restrict__ w2) {
    int idx = blockIdx.x * blockDim.x + threadIdx.x;   // 2 * 9*256*256
    int which = idx >= 9*256*256;
    int j = which ? idx - 9*256*256 : idx;
    int ic  = j & 255;
    int oc  = (j >> 8) & 255;
    int tap = j >> 16;
    const float* w = which ? w2 : w1;
    __nv_bfloat16 v = __float2bfloat16(w[((size_t)oc * CH + ic) * 9 + tap]);
    if (which == 0) g_wb1[j] = v; else g_wb2[j] = v;
}

// ---------------- bf16 HMMA implicit-GEMM conv ----------------
// CTA: 128 px x 128 oc; 4 warps (64x64 warp tile); 2 CTAs/SM.
// cp.async spread across mma groups; MODE 1 output staged via smem -> coalesced NCHW.
template <int MODE>
__global__ __launch_bounds__(128, 2) void k_conv(
    const float* __restrict__ ps_in,  const float* __restrict__ ps_w,
    const float* __restrict__ ps_out, const float* __restrict__ pz_out,
    const float* __restrict__ ps_x,   const float* __restrict__ ps_add,
    const float* __restrict__ pz_add,
    float* __restrict__ out)
{
    extern __shared__ char smem[];
    const uint32_t sb = smem_u32(smem);
    const __nv_bfloat16* act = (MODE == 0) ? g_axs : g_amid;
    const __nv_bfloat16* wq  = (MODE == 0) ? g_wb1 : g_wb2;

    const int tid  = threadIdx.x;
    const int lane = tid & 31;
    const int wid  = tid >> 5;
    const int wm   = wid & 1;
    const int wn   = wid >> 1;
    const int P0   = blockIdx.x * MT;
    const int ocb  = blockIdx.y * 128;

    float acc[4][8][4];
#pragma unroll
    for (int mt = 0; mt < 4; mt++)
#pragma unroll
        for (int nt = 0; nt < 8; nt++)
#pragma unroll
            for (int j = 0; j < 4; j++) acc[mt][nt][j] = 0.f;

    // quarter-stage loader: part p issues 2 A-cp16 + 2 B-cp16 per thread
    auto load_part = [&](int s, int p) {
        int tap = s >> 2;
        int ic0 = (s & 3) * 64;
        int off = (tap / 3) * 30 + (tap % 3);
        uint32_t bufA = sb + (s % NBUF) * STAGE_BYTES;
        uint32_t bufB = bufA + A_BYTES;
        const char* ga = (const char*)act + (size_t)(P0 + off) * 512 + ic0 * 2;
        const char* gb = (const char*)wq + ((size_t)tap * 256 + ocb) * 512 + ic0 * 2;
#pragma unroll
        for (int i = 0; i < 2; i++) {
            int idx = tid + (p * 2 + i) * 128;      // 0..1023
            int row = idx >> 3, c16 = idx & 7;
            uint32_t sw = (uint32_t)(row * 128 + ((c16 ^ (row & 7)) << 4));
            cp16(bufA + sw, ga + (size_t)row * 512 + c16 * 16);
            cp16(bufB + sw, gb + (size_t)row * 512 + c16 * 16);
        }
    };

#pragma unroll
    for (int p = 0; p < 4; p++) load_part(0, p);
    CP_COMMIT();
#pragma unroll
    for (int p = 0; p < 4; p++) load_part(1, p);
    CP_COMMIT();

    const int lrow = (lane & 7) + ((lane >> 3) & 1) * 8;
    const int lchk = lane >> 4;

    uint32_t afb[2][4][4];
    uint32_t bfb[2][8][2];
    auto load_frags = [&](uint32_t bufA, uint32_t bufB, int g, int d) {
        const int c = (g << 1) | lchk;
#pragma unroll
        for (int mt = 0; mt < 4; mt++) {
            int r = wm * 64 + mt * 16 + lrow;
            ldm4(afb[d][mt], bufA + r * 128 + ((c ^ (r & 7)) << 4));
        }
#pragma unroll
        for (int nt2 = 0; nt2 < 4; nt2++) {
            int r = wn * 64 + nt2 * 16 + lrow;
            uint32_t rr[4];
            ldm4(rr, bufB + r * 128 + ((c ^ (r & 7)) << 4));
            bfb[d][nt2*2][0]   = rr[0]; bfb[d][nt2*2][1]   = rr[2];
            bfb[d][nt2*2+1][0] = rr[1]; bfb[d][nt2*2+1][1] = rr[3];
        }
    };

#pragma unroll 1
    for (int s = 0; s < NSTAGE; s++) {
        if (s == NSTAGE - 1) cp_wait<0>(); else cp_wait<1>();
        __syncthreads();

        uint32_t bufA = sb + (s % NBUF) * STAGE_BYTES;
        uint32_t bufB = bufA + A_BYTES;
        const bool more = (s + 2 < NSTAGE);

        load_frags(bufA, bufB, 0, 0);
#pragma unroll
        for (int g = 0; g < 4; g++) {
            if (g < 3) load_frags(bufA, bufB, g + 1, (g + 1) & 1);
            if (more)  load_part(s + 2, g);      // spread LDGSTS across groups
            const int d = g & 1;
#pragma unroll
            for (int mt = 0; mt < 4; mt++)
#pragma unroll
                for (int nt = 0; nt < 8; nt++)
                    mma_bf16(acc[mt][nt], afb[d][mt], bfb[d][nt]);
        }
        if (more) CP_COMMIT();
    }

    // ---------------- epilogue ----------------
    const float M  = __fdiv_rn(__fmul_rn(*ps_in, *ps_w), *ps_out);
    const float zo = *pz_out;
    const float lo = -zo, hi = 255.f - zo;     // clamp in shifted domain (zo integer)
    const int qrow = lane >> 2;
    const int cc   = (lane & 3) << 1;

    if (MODE == 0) {
        const int ocw = ocb + wn * 64;
#pragma unroll
        for (int mt = 0; mt < 4; mt++) {
#pragma unroll
            for (int h = 0; h < 2; h++) {
                int r  = wm * 64 + mt * 16 + qrow + h * 8;
                int P  = P0 + r;
                int n  = P / HPX;
                int q  = P - n * HPX;
                int oh = q / 30, ow = q - oh * 30;
                if (oh >= 28 || ow >= 28) continue;
                size_t base = (size_t)(P + 31) * 256 + ocw + cc;
#pragma unroll
                for (int nt = 0; nt < 8; nt++) {
                    float t0 = fminf(fmaxf(rintf(__fmul_rn(M, acc[mt][nt][h*2])),   lo), hi);
                    float t1 = fminf(fmaxf(rintf(__fmul_rn(M, acc[mt][nt][h*2+1])), lo), hi);
                    __nv_bfloat162 u;
                    u.x = __float2bfloat16(t0);
                    u.y = __float2bfloat16(t1);
                    *(__nv_bfloat162*)(g_amid + base + nt * 8) = u;
                }
            }
        }
    } else {
        // phase 1: requant + residual, stage fp32 tile in smem [128 px][128 oc], stride 129
        const float ra = __fdiv_rn(*ps_x,   *ps_add);
        const float rb = __fdiv_rn(*ps_out, *ps_add);
        const float za = *pz_add;
        float* sf = (float*)smem;
        __syncthreads();                         // mainloop smem reads done (all warps)
        const int ocl = wn * 64 + cc;            // local oc of acc columns (pair base)
#pragma unroll
        for (int mt = 0; mt < 4; mt++) {
#pragma unroll
            for (int h = 0; h < 2; h++) {
                int r  = wm * 64 + mt * 16 + qrow + h * 8;   // local px
                int P  = P0 + r;
                int n  = P / HPX;
                int q  = P - n * HPX;
                int oh = q / 30, ow = q - oh * 30;
                if (oh >= 28 || ow >= 28) continue;
                size_t xbase = (size_t)(P + 31) * 256 + ocb + ocl;
#pragma unroll
                for (int nt = 0; nt < 8; nt++) {
                    float t0 = fminf(fmaxf(rintf(__fmul_rn(M, acc[mt][nt][h*2])),   lo), hi);
                    float t1 = fminf(fmaxf(rintf(__fmul_rn(M, acc[mt][nt][h*2+1])), lo), hi);
                    float xv0 = __bfloat162float(g_axs[xbase + nt * 8]);
                    float xv1 = __bfloat162float(g_axs[xbase + nt * 8 + 1]);
                    float y0 = __fadd_rn(__fmul_rn(ra, xv0), __fmul_rn(rb, t0));
                    float y1 = __fadd_rn(__fmul_rn(ra, xv1), __fmul_rn(rb, t1));
                    sf[r * 129 + ocl + nt * 8]     = fminf(fmaxf(rintf(y0) + za, 0.f), 255.f);
                    sf[r * 129 + ocl + nt * 8 + 1] = fminf(fmaxf(rintf(y1) + za, 0.f), 255.f);
                }
            }
        }
        __syncthreads();
        // phase 2: coalesced NCHW write; warp owns 32 oc, lanes map to consecutive ow
        const int prow0 = P0 / 30;
#pragma unroll 1
        for (int rr = 0; rr < 6; rr++) {
            int R  = prow0 + rr;                  // global padded row
            int ps = max(P0, R * 30), pe = min(P0 + MT, R * 30 + 30);
            if (ps >= pe) continue;
            int n  = R / 30, oh = R % 30;
            if (oh >= 28) continue;
            int owb = ps - R * 30;
            int cnt = pe - ps;
            int ow  = owb + lane;
            bool ok = (lane < cnt) && (ow < 28);
            int pxl = ps - P0 + lane;
#pragma unroll
            for (int i = 0; i < 32; i++) {
                int oc = wid * 32 + i;
                if (ok)
                    out[(((size_t)n * CH + ocb + oc) * HH + oh) * WW + ow] = sf[pxl * 129 + oc];
            }
        }
    }
}

// ---------------- launch ----------------
extern "C" void kernel_launch(void* const* d_in, const int* in_sizes, int n_in,
                              void* d_out, int out_size) {
    const float* x    = (const float*)d_in[0];
    const float* w1   = (const float*)d_in[1];
    const float* w2   = (const float*)d_in[2];
    const float* s_x  = (const float*)d_in[3];
    const float* z_x  = (const float*)d_in[4];
    const float* s_w1 = (const float*)d_in[5];
    const float* s_c1 = (const float*)d_in[6];
    const float* z_c1 = (const float*)d_in[7];
    const float* s_w2 = (const float*)d_in[8];
    const float* s_c2 = (const float*)d_in[9];
    const float* z_c2 = (const float*)d_in[10];
    const float* s_ad = (const float*)d_in[11];
    const float* z_ad = (const float*)d_in[12];
    float* out = (float*)d_out;

    cudaFuncSetAttribute(k_conv<0>, cudaFuncAttributeMaxDynamicSharedMemorySize, SMEM_TOTAL);
    cudaFuncSetAttribute(k_conv<1>, cudaFuncAttributeMaxDynamicSharedMemorySize, SMEM_TOTAL);

    int zthreads = 2 * RING_SLOTS * 32;
    k_zero_halo<<<(zthreads + 255) / 256, 256>>>();
    k_pack_x<<<NB * HH, 256>>>(x, z_x);
    k_pack_w2<<<2 * 9 * 256, 256>>>(w1, w2);

    dim3 grid(NMT, 2);
    k_conv<0><<<grid, 128, SMEM_TOTAL>>>(s_x, s_w1, s_c1, z_c1,
                                         s_x, s_ad, z_ad, nullptr);
    k_conv<1><<<grid, 128, SMEM_TOTAL>>>(s_c1, s_w2, s_c2, z_c2,
                                         s_x, s_ad, z_ad, out);
}

// round 15
// speedup vs baseline: 1.0586x; 1.0586x over previous
#include <cuda_runtime.h>
#include <cuda_bf16.h>
#include <stdint.h>

// ---------------- problem constants ----------------
#define NB   64
#define CH   256
#define HH   28
#define WW   28
#define HPX  900              // 30*30 padded pixels per image
#define NPIX (NB*HPX)         // 57600 padded
#define NVPX (NB*HH*WW)       // 50176 valid output pixels
#define NPIX_PAD 57728
#define MT   128              // valid pixels per CTA
#define NMT  (NVPX/MT)        // 392
#define NSTAGE 36             // 9 taps * 4 ic-chunks (64 ic)
#define NBUF 3
#define A_BYTES 16384
#define B_BYTES 16384
#define STAGE_BYTES (A_BYTES + B_BYTES)        // 32768
#define SMEM_TOTAL (NBUF*STAGE_BYTES)          // 98304 -> 2 CTAs/SM

// ---------------- device scratch ----------------
__device__ __align__(16) __nv_bfloat16 g_axs [(size_t)NPIX_PAD*CH];  // x - z_x, pad 0
__device__ __align__(16) __nv_bfloat16 g_amid[(size_t)NPIX_PAD*CH];  // mid - z_c1, pad 0
__device__ __align__(16) __nv_bfloat16 g_wb1[9*CH*CH];               // [tap][oc][ic]
__device__ __align__(16) __nv_bfloat16 g_wb2[9*CH*CH];

// ---------------- PTX helpers ----------------
__device__ __forceinline__ uint32_t smem_u32(const void* p) {
    uint32_t a;
    asm("{ .reg .u64 t; cvta.to.shared.u64 t, %1; cvt.u32.u64 %0, t; }" : "=r"(a) : "l"(p));
    return a;
}
__device__ __forceinline__ void cp16(uint32_t sdst, const void* gsrc) {
    asm volatile("cp.async.cg.shared.global [%0], [%1], 16;" :: "r"(sdst), "l"(gsrc));
}
#define CP_COMMIT() asm volatile("cp.async.commit_group;" ::: "memory")
template <int N> __device__ __forceinline__ void cp_wait() {
    asm volatile("cp.async.wait_group %0;" :: "n"(N) : "memory");
}
__device__ __forceinline__ void ldm4(uint32_t* r, uint32_t addr) {
    asm volatile("ldmatrix.sync.aligned.m8n8.x4.shared.b16 {%0,%1,%2,%3}, [%4];"
        : "=r"(r[0]), "=r"(r[1]), "=r"(r[2]), "=r"(r[3]) : "r"(addr));
}
__device__ __forceinline__ void mma_bf16(float* d, const uint32_t* a, const uint32_t* b) {
    asm volatile("mma.sync.aligned.m16n8k16.row.col.f32.bf16.bf16.f32 "
        "{%0,%1,%2,%3},{%4,%5,%6,%7},{%8,%9},{%0,%1,%2,%3};"
        : "+f"(d[0]), "+f"(d[1]), "+f"(d[2]), "+f"(d[3])
        : "r"(a[0]), "r"(a[1]), "r"(a[2]), "r"(a[3]), "r"(b[0]), "r"(b[1]));
}

// valid pixel -> padded pixel index of its CENTER
__device__ __forceinline__ int pad_idx(int vp) {
    int n  = vp / 784;
    int r  = vp - n * 784;
    int oh = r / 28;
    int ow = r - oh * 28;
    return n * HPX + (oh + 1) * 30 + ow + 1;
}

// ---------------- packing kernels ----------------
#define RING_SLOTS (64*116)
__global__ void k_zero_halo() {
    int idx = blockIdx.x * blockDim.x + threadIdx.x;
    int total = RING_SLOTS * 32;
    if (idx >= 2 * total) return;
    int arr = idx >= total;
    int t = arr ? idx - total : idx;
    int chunk = t & 31;
    int slot  = t >> 5;
    int img = slot / 116, i = slot % 116;
    int q;
    if (i < 30)       q = i;
    else if (i < 60)  q = 870 + (i - 30);
    else if (i < 88)  q = (i - 60 + 1) * 30;
    else              q = (i - 88 + 1) * 30 + 29;
    size_t P = (size_t)img * HPX + q;
    int4 z = make_int4(0, 0, 0, 0);
    if (arr == 0) ((int4*)(g_axs  + P * 256))[chunk] = z;
    else          ((int4*)(g_amid + P * 256))[chunk] = z;
}

__global__ void k_pack_x(const float* __restrict__ x, const float* __restrict__ pzx) {
    __shared__ __nv_bfloat16 s[28 * 258];
    int n  = blockIdx.x / 28;
    int oh = blockIdx.x % 28;
    float zx = *pzx;
    for (int i = threadIdx.x; i < 28 * 256; i += 256) {
        int c = i / 28, ow = i % 28;
        float g = x[(((size_t)n * CH + c) * HH + oh) * WW + ow];
        s[ow * 258 + c] = __float2bfloat16(__fsub_rn(g, zx));
    }
    __syncthreads();
    for (int i = threadIdx.x; i < 28 * 256; i += 256) {
        int ow = i >> 8, c = i & 255;
        g_axs[((size_t)n * HPX + (oh + 1) * 30 + ow + 1) * CH + c] = s[ow * 258 + c];
    }
}

__global__ void k_pack_w2(const float* __restrict__ w1, const float* __restrict__ w2) {
    int idx = blockIdx.x * blockDim.x + threadIdx.x;
    int which = idx >= 9*256*256;
    int j = which ? idx - 9*256*256 : idx;
    int ic  = j & 255;
    int oc  = (j >> 8) & 255;
    int tap = j >> 16;
    const float* w = which ? w2 : w1;
    __nv_bfloat16 v = __float2bfloat16(w[((size_t)oc * CH + ic) * 9 + tap]);
    if (which == 0) g_wb1[j] = v; else g_wb2[j] = v;
}

// ---------------- bf16 HMMA implicit-GEMM conv (valid pixels only) ----------------
// CTA: 128 valid px x 128 oc; 4 warps (64x64 warp tile); 2 CTAs/SM; grid 392x2.
template <int MODE>
__global__ __launch_bounds__(128, 2) void k_conv(
    const float* __restrict__ ps_in,  const float* __restrict__ ps_w,
    const float* __restrict__ ps_out, const float* __restrict__ pz_out,
    const float* __restrict__ ps_x,   const float* __restrict__ ps_add,
    const float* __restrict__ pz_add,
    const float* __restrict__ xin,    const float* __restrict__ pzx,
    float* __restrict__ out)
{
    extern __shared__ char smem[];
    const uint32_t sb = smem_u32(smem);
    const __nv_bfloat16* act = (MODE == 0) ? g_axs : g_amid;
    const __nv_bfloat16* wq  = (MODE == 0) ? g_wb1 : g_wb2;

    const int tid  = threadIdx.x;
    const int lane = tid & 31;
    const int wid  = tid >> 5;
    const int wm   = wid & 1;
    const int wn   = wid >> 1;
    const int P0   = blockIdx.x * MT;
    const int ocb  = blockIdx.y * 128;

    // precompute the 8 A-row gather offsets: TOP-LEFT of each pixel's 3x3 window
    // (= center - 31); tap offset 'off' is added on top of this.
    uint32_t poff[8];
    {
        int row0 = tid >> 3;
#pragma unroll
        for (int i = 0; i < 8; i++)
            poff[i] = (uint32_t)(pad_idx(P0 + row0 + i * 16) - 31) * 512u;
    }
    const int c16 = tid & 7;

    float acc[4][8][4];
#pragma unroll
    for (int mt = 0; mt < 4; mt++)
#pragma unroll
        for (int nt = 0; nt < 8; nt++)
#pragma unroll
            for (int j = 0; j < 4; j++) acc[mt][nt][j] = 0.f;

    // stage loader: A 8 gathered rows + B 8 linear rows per thread
    auto load_stage = [&](int s) {
        int tap = s >> 2;
        int ic0 = (s & 3) * 64;
        int off = (tap / 3) * 30 + (tap % 3);
        uint32_t bufA = sb + (s % NBUF) * STAGE_BYTES;
        uint32_t bufB = bufA + A_BYTES;
        const char* gaB = (const char*)act + (size_t)off * 512 + ic0 * 2 + c16 * 16;
        const char* gb  = (const char*)wq + ((size_t)tap * 256 + ocb) * 512 + ic0 * 2;
        int row0 = tid >> 3;
        uint32_t swb = (uint32_t)(row0 * 128 + ((c16 ^ (row0 & 7)) << 4));
#pragma unroll
        for (int i = 0; i < 8; i++) {
            cp16(bufA + swb + i * 2048, gaB + poff[i]);
        }
#pragma unroll
        for (int i = 0; i < 8; i++) {
            int row = row0 + i * 16;
            uint32_t sw = (uint32_t)(row * 128 + ((c16 ^ (row & 7)) << 4));
            cp16(bufB + sw, gb + (size_t)row * 512 + c16 * 16);
        }
        CP_COMMIT();
    };

    load_stage(0); load_stage(1);

    const int lrow = (lane & 7) + ((lane >> 3) & 1) * 8;
    const int lchk = lane >> 4;

    uint32_t afb[2][4][4];
    uint32_t bfb[2][8][2];
    auto load_frags = [&](uint32_t bufA, uint32_t bufB, int g, int d) {
        const int c = (g << 1) | lchk;
#pragma unroll
        for (int mt = 0; mt < 4; mt++) {
            int r = wm * 64 + mt * 16 + lrow;
            ldm4(afb[d][mt], bufA + r * 128 + ((c ^ (r & 7)) << 4));
        }
#pragma unroll
        for (int nt2 = 0; nt2 < 4; nt2++) {
            int r = wn * 64 + nt2 * 16 + lrow;
            uint32_t rr[4];
            ldm4(rr, bufB + r * 128 + ((c ^ (r & 7)) << 4));
            bfb[d][nt2*2][0]   = rr[0]; bfb[d][nt2*2][1]   = rr[2];
            bfb[d][nt2*2+1][0] = rr[1]; bfb[d][nt2*2+1][1] = rr[3];
        }
    };

#pragma unroll 1
    for (int s = 0; s < NSTAGE; s++) {
        if (s == NSTAGE - 1) cp_wait<0>(); else cp_wait<1>();
        __syncthreads();

        uint32_t bufA = sb + (s % NBUF) * STAGE_BYTES;
        uint32_t bufB = bufA + A_BYTES;

        load_frags(bufA, bufB, 0, 0);
        if (s + 2 < NSTAGE) load_stage(s + 2);

#pragma unroll
        for (int g = 0; g < 4; g++) {
            if (g < 3) load_frags(bufA, bufB, g + 1, (g + 1) & 1);
            const int d = g & 1;
#pragma unroll
            for (int mt = 0; mt < 4; mt++)
#pragma unroll
                for (int nt = 0; nt < 8; nt++)
                    mma_bf16(acc[mt][nt], afb[d][mt], bfb[d][nt]);
        }
    }

    // ---------------- epilogue ----------------
    const float M  = __fdiv_rn(__fmul_rn(*ps_in, *ps_w), *ps_out);
    const float zo = *pz_out;
    const float lo = -zo, hi = 255.f - zo;     // clamp in shifted domain
    const int qrow = lane >> 2;
    const int cc   = (lane & 3) << 1;

    if (MODE == 0) {
        const int ocw = ocb + wn * 64;
#pragma unroll
        for (int mt = 0; mt < 4; mt++) {
#pragma unroll
            for (int h = 0; h < 2; h++) {
                int r  = wm * 64 + mt * 16 + qrow + h * 8;
                size_t base = (size_t)pad_idx(P0 + r) * 256 + ocw + cc;
#pragma unroll
                for (int nt = 0; nt < 8; nt++) {
                    float t0 = fminf(fmaxf(rintf(__fmul_rn(M, acc[mt][nt][h*2])),   lo), hi);
                    float t1 = fminf(fmaxf(rintf(__fmul_rn(M, acc[mt][nt][h*2+1])), lo), hi);
                    __nv_bfloat162 u;
                    u.x = __float2bfloat16(t0);
                    u.y = __float2bfloat16(t1);
                    *(__nv_bfloat162*)(g_amid + base + nt * 8) = u;
                }
            }
        }
    } else {
        // phase 1: requantized shifted conv2 value -> smem tile [128 px][128 oc] stride 129
        float* sf = (float*)smem;
        __syncthreads();                        // all warps done reading stage bufs
        const int ocl = wn * 64 + cc;
#pragma unroll
        for (int mt = 0; mt < 4; mt++) {
#pragma unroll
            for (int h = 0; h < 2; h++) {
                int r = wm * 64 + mt * 16 + qrow + h * 8;
#pragma unroll
                for (int nt = 0; nt < 8; nt++) {
                    sf[r * 129 + ocl + nt * 8] =
                        fminf(fmaxf(rintf(__fmul_rn(M, acc[mt][nt][h*2])),   lo), hi);
                    sf[r * 129 + ocl + nt * 8 + 1] =
                        fminf(fmaxf(rintf(__fmul_rn(M, acc[mt][nt][h*2+1])), lo), hi);
                }
            }
        }
        __syncthreads();
        // phase 2: coalesced residual qadd + NCHW write (lane <-> consecutive valid px)
        const float ra = __fdiv_rn(*ps_x,   *ps_add);
        const float rb = __fdiv_rn(*ps_out, *ps_add);
        const float za = *pz_add;
        const float zx = *pzx;
#pragma unroll 1
        for (int b4 = 0; b4 < 4; b4++) {
            int pl = b4 * 32 + lane;
            int vp = P0 + pl;
            int n  = vp / 784;
            int rr = vp - n * 784;
            int oh = rr / 28;
            int ow = rr - oh * 28;
            size_t base = (((size_t)n * CH + ocb) * HH + oh) * WW + ow;
#pragma unroll
            for (int i = 0; i < 32; i++) {
                int oc = wid * 32 + i;
                size_t a = base + (size_t)oc * 784;
                float xf = xin[a];
                float y  = __fadd_rn(__fmul_rn(ra, __fsub_rn(xf, zx)),
                                     __fmul_rn(rb, sf[pl * 129 + oc]));
                out[a] = fminf(fmaxf(rintf(y) + za, 0.f), 255.f);
            }
        }
    }
}

// ---------------- launch ----------------
extern "C" void kernel_launch(void* const* d_in, const int* in_sizes, int n_in,
                              void* d_out, int out_size) {
    const float* x    = (const float*)d_in[0];
    const float* w1   = (const float*)d_in[1];
    const float* w2   = (const float*)d_in[2];
    const float* s_x  = (const float*)d_in[3];
    const float* z_x  = (const float*)d_in[4];
    const float* s_w1 = (const float*)d_in[5];
    const float* s_c1 = (const float*)d_in[6];
    const float* z_c1 = (const float*)d_in[7];
    const float* s_w2 = (const float*)d_in[8];
    const float* s_c2 = (const float*)d_in[9];
    const float* z_c2 = (const float*)d_in[10];
    const float* s_ad = (const float*)d_in[11];
    const float* z_ad = (const float*)d_in[12];
    float* out = (float*)d_out;

    cudaFuncSetAttribute(k_conv<0>, cudaFuncAttributeMaxDynamicSharedMemorySize, SMEM_TOTAL);
    cudaFuncSetAttribute(k_conv<1>, cudaFuncAttributeMaxDynamicSharedMemorySize, SMEM_TOTAL);

    int zthreads = 2 * RING_SLOTS * 32;
    k_zero_halo<<<(zthreads + 255) / 256, 256>>>();
    k_pack_x<<<NB * HH, 256>>>(x, z_x);
    k_pack_w2<<<2 * 9 * 256, 256>>>(w1, w2);

    dim3 grid(NMT, 2);
    k_conv<0><<<grid, 128, SMEM_TOTAL>>>(s_x, s_w1, s_c1, z_c1,
                                         s_x, s_ad, z_ad, nullptr, z_x, nullptr);
    k_conv<1><<<grid, 128, SMEM_TOTAL>>>(s_c1, s_w2, s_c2, z_c2,
                                         s_x, s_ad, z_ad, x, z_x, out);
}

// round 16
// speedup vs baseline: 1.1334x; 1.0707x over previous
#include <cuda_runtime.h>
#include <cuda_bf16.h>
#include <stdint.h>

// ---------------- problem constants ----------------
#define NB   64
#define CH   256
#define HH   28
#define WW   28
#define HPX  900              // 30*30 padded pixels per image
#define NPIX (NB*HPX)         // 57600 padded
#define NVPX (NB*HH*WW)       // 50176 valid output pixels
#define NPIX_PAD 57728
#define MT   64               // valid pixels per CTA
#define NMT  (NVPX/MT)        // 784
#define NSTAGE 36             // 9 taps * 4 ic-chunks (64 ic)
#define NBUF 3
#define A_BYTES 8192          // 64 rows * 128B
#define B_BYTES 16384         // 128 rows * 128B
#define STAGE_BYTES (A_BYTES + B_BYTES)        // 24576
#define SMEM_TOTAL (NBUF*STAGE_BYTES)          // 73728 -> 3 CTAs/SM

// ---------------- device scratch ----------------
__device__ __align__(16) __nv_bfloat16 g_axs [(size_t)NPIX_PAD*CH];  // x - z_x, pad 0
__device__ __align__(16) __nv_bfloat16 g_amid[(size_t)NPIX_PAD*CH];  // mid - z_c1, pad 0
__device__ __align__(16) __nv_bfloat16 g_wb1[9*CH*CH];               // [tap][oc][ic]
__device__ __align__(16) __nv_bfloat16 g_wb2[9*CH*CH];

// ---------------- PTX helpers ----------------
__device__ __forceinline__ uint32_t smem_u32(const void* p) {
    uint32_t a;
    asm("{ .reg .u64 t; cvta.to.shared.u64 t, %1; cvt.u32.u64 %0, t; }" : "=r"(a) : "l"(p));
    return a;
}
__device__ __forceinline__ void cp16(uint32_t sdst, const void* gsrc) {
    asm volatile("cp.async.cg.shared.global [%0], [%1], 16;" :: "r"(sdst), "l"(gsrc));
}
#define CP_COMMIT() asm volatile("cp.async.commit_group;" ::: "memory")
template <int N> __device__ __forceinline__ void cp_wait() {
    asm volatile("cp.async.wait_group %0;" :: "n"(N) : "memory");
}
__device__ __forceinline__ void ldm4(uint32_t* r, uint32_t addr) {
    asm volatile("ldmatrix.sync.aligned.m8n8.x4.shared.b16 {%0,%1,%2,%3}, [%4];"
        : "=r"(r[0]), "=r"(r[1]), "=r"(r[2]), "=r"(r[3]) : "r"(addr));
}
__device__ __forceinline__ void mma_bf16(float* d, const uint32_t* a, const uint32_t* b) {
    asm volatile("mma.sync.aligned.m16n8k16.row.col.f32.bf16.bf16.f32 "
        "{%0,%1,%2,%3},{%4,%5,%6,%7},{%8,%9},{%0,%1,%2,%3};"
        : "+f"(d[0]), "+f"(d[1]), "+f"(d[2]), "+f"(d[3])
        : "r"(a[0]), "r"(a[1]), "r"(a[2]), "r"(a[3]), "r"(b[0]), "r"(b[1]));
}

// valid pixel -> padded pixel index of its CENTER
__device__ __forceinline__ int pad_idx(int vp) {
    int n  = vp / 784;
    int r  = vp - n * 784;
    int oh = r / 28;
    int ow = r - oh * 28;
    return n * HPX + (oh + 1) * 30 + ow + 1;
}

// ---------------- packing kernels ----------------
#define RING_SLOTS (64*116)
__global__ void k_zero_halo() {
    int idx = blockIdx.x * blockDim.x + threadIdx.x;
    int total = RING_SLOTS * 32;
    if (idx >= 2 * total) return;
    int arr = idx >= total;
    int t = arr ? idx - total : idx;
    int chunk = t & 31;
    int slot  = t >> 5;
    int img = slot / 116, i = slot % 116;
    int q;
    if (i < 30)       q = i;
    else if (i < 60)  q = 870 + (i - 30);
    else if (i < 88)  q = (i - 60 + 1) * 30;
    else              q = (i - 88 + 1) * 30 + 29;
    size_t P = (size_t)img * HPX + q;
    int4 z = make_int4(0, 0, 0, 0);
    if (arr == 0) ((int4*)(g_axs  + P * 256))[chunk] = z;
    else          ((int4*)(g_amid + P * 256))[chunk] = z;
}

__global__ void k_pack_x(const float* __restrict__ x, const float* __restrict__ pzx) {
    __shared__ __nv_bfloat16 s[28 * 258];
    int n  = blockIdx.x / 28;
    int oh = blockIdx.x % 28;
    float zx = *pzx;
    for (int i = threadIdx.x; i < 28 * 256; i += 256) {
        int c = i / 28, ow = i % 28;
        float g = x[(((size_t)n * CH + c) * HH + oh) * WW + ow];
        s[ow * 258 + c] = __float2bfloat16(__fsub_rn(g, zx));
    }
    __syncthreads();
    for (int i = threadIdx.x; i < 28 * 256; i += 256) {
        int ow = i >> 8, c = i & 255;
        g_axs[((size_t)n * HPX + (oh + 1) * 30 + ow + 1) * CH + c] = s[ow * 258 + c];
    }
}

__global__ void k_pack_w2(const float* __restrict__ w1, const float* __restrict__ w2) {
    int idx = blockIdx.x * blockDim.x + threadIdx.x;
    int which = idx >= 9*256*256;
    int j = which ? idx - 9*256*256 : idx;
    int ic  = j & 255;
    int oc  = (j >> 8) & 255;
    int tap = j >> 16;
    const float* w = which ? w2 : w1;
    __nv_bfloat16 v = __float2bfloat16(w[((size_t)oc * CH + ic) * 9 + tap]);
    if (which == 0) g_wb1[j] = v; else g_wb2[j] = v;
}

// ---------------- bf16 HMMA implicit-GEMM conv ----------------
// CTA: 64 valid px x 128 oc; 4 warps, warp tile 32x64; 3 CTAs/SM; grid 784x2.
template <int MODE>
__global__ __launch_bounds__(128, 3) void k_conv(
    const float* __restrict__ ps_in,  const float* __restrict__ ps_w,
    const float* __restrict__ ps_out, const float* __restrict__ pz_out,
    const float* __restrict__ ps_x,   const float* __restrict__ ps_add,
    const float* __restrict__ pz_add,
    const float* __restrict__ xin,    const float* __restrict__ pzx,
    float* __restrict__ out)
{
    extern __shared__ char smem[];
    const uint32_t sb = smem_u32(smem);
    const __nv_bfloat16* act = (MODE == 0) ? g_axs : g_amid;
    const __nv_bfloat16* wq  = (MODE == 0) ? g_wb1 : g_wb2;

    const int tid  = threadIdx.x;
    const int lane = tid & 31;
    const int wid  = tid >> 5;
    const int wm   = wid & 1;           // 2 m-warps (32 px each)
    const int wn   = wid >> 1;          // 2 n-warps (64 oc each)
    const int P0   = blockIdx.x * MT;
    const int ocb  = blockIdx.y * 128;

    // A-row gather offsets: TOP-LEFT of each pixel's 3x3 window (= center - 31)
    uint32_t poff[4];
    {
        int row0 = tid >> 3;            // 0..15
#pragma unroll
        for (int i = 0; i < 4; i++)
            poff[i] = (uint32_t)(pad_idx(P0 + row0 + i * 16) - 31) * 512u;
    }
    const int c16 = tid & 7;

    float acc[2][8][4];
#pragma unroll
    for (int mt = 0; mt < 2; mt++)
#pragma unroll
        for (int nt = 0; nt < 8; nt++)
#pragma unroll
            for (int j = 0; j < 4; j++) acc[mt][nt][j] = 0.f;

    // stage loader: A 4 gathered rows + B 8 linear rows per thread
    auto load_stage = [&](int s) {
        int tap = s >> 2;
        int ic0 = (s & 3) * 64;
        int off = (tap / 3) * 30 + (tap % 3);
        uint32_t bufA = sb + (s % NBUF) * STAGE_BYTES;
        uint32_t bufB = bufA + A_BYTES;
        const char* gaB = (const char*)act + (size_t)off * 512 + ic0 * 2 + c16 * 16;
        const char* gb  = (const char*)wq + ((size_t)tap * 256 + ocb) * 512 + ic0 * 2;
        int row0 = tid >> 3;
        uint32_t swb = (uint32_t)(row0 * 128 + ((c16 ^ (row0 & 7)) << 4));
#pragma unroll
        for (int i = 0; i < 4; i++) {
            cp16(bufA + swb + i * 2048, gaB + poff[i]);
        }
#pragma unroll
        for (int i = 0; i < 8; i++) {
            int row = row0 + i * 16;
            uint32_t sw = (uint32_t)(row * 128 + ((c16 ^ (row & 7)) << 4));
            cp16(bufB + sw, gb + (size_t)row * 512 + c16 * 16);
        }
        CP_COMMIT();
    };

    load_stage(0); load_stage(1);

    const int lrow = (lane & 7) + ((lane >> 3) & 1) * 8;
    const int lchk = lane >> 4;

#pragma unroll 1
    for (int s = 0; s < NSTAGE; s++) {
        if (s == NSTAGE - 1) cp_wait<0>(); else cp_wait<1>();
        __syncthreads();

        uint32_t bufA = sb + (s % NBUF) * STAGE_BYTES;
        uint32_t bufB = bufA + A_BYTES;

        if (s + 2 < NSTAGE) load_stage(s + 2);

#pragma unroll
        for (int g = 0; g < 4; g++) {
            const int c = (g << 1) | lchk;
            uint32_t af[2][4];
#pragma unroll
            for (int mt = 0; mt < 2; mt++) {
                int r = wm * 32 + mt * 16 + lrow;
                ldm4(af[mt], bufA + r * 128 + ((c ^ (r & 7)) << 4));
            }
            uint32_t bf[8][2];
#pragma unroll
            for (int nt2 = 0; nt2 < 4; nt2++) {
                int r = wn * 64 + nt2 * 16 + lrow;
                uint32_t rr[4];
                ldm4(rr, bufB + r * 128 + ((c ^ (r & 7)) << 4));
                bf[nt2*2][0]   = rr[0]; bf[nt2*2][1]   = rr[2];
                bf[nt2*2+1][0] = rr[1]; bf[nt2*2+1][1] = rr[3];
            }
#pragma unroll
            for (int mt = 0; mt < 2; mt++)
#pragma unroll
                for (int nt = 0; nt < 8; nt++)
                    mma_bf16(acc[mt][nt], af[mt], bf[nt]);
        }
    }

    // ---------------- epilogue ----------------
    const float M  = __fdiv_rn(__fmul_rn(*ps_in, *ps_w), *ps_out);
    const float zo = *pz_out;
    const float lo = -zo, hi = 255.f - zo;     // clamp in shifted domain
    const int qrow = lane >> 2;
    const int cc   = (lane & 3) << 1;

    if (MODE == 0) {
        const int ocw = ocb + wn * 64;
#pragma unroll
        for (int mt = 0; mt < 2; mt++) {
#pragma unroll
            for (int h = 0; h < 2; h++) {
                int r  = wm * 32 + mt * 16 + qrow + h * 8;
                size_t base = (size_t)pad_idx(P0 + r) * 256 + ocw + cc;
#pragma unroll
                for (int nt = 0; nt < 8; nt++) {
                    float t0 = fminf(fmaxf(rintf(__fmul_rn(M, acc[mt][nt][h*2])),   lo), hi);
                    float t1 = fminf(fmaxf(rintf(__fmul_rn(M, acc[mt][nt][h*2+1])), lo), hi);
                    __nv_bfloat162 u;
                    u.x = __float2bfloat16(t0);
                    u.y = __float2bfloat16(t1);
                    *(__nv_bfloat162*)(g_amid + base + nt * 8) = u;
                }
            }
        }
    } else {
        // phase 1: requantized shifted conv2 value -> smem tile [64 px][128 oc] stride 129
        float* sf = (float*)smem;
        __syncthreads();                        // all warps done reading stage bufs
        const int ocl = wn * 64 + cc;
#pragma unroll
        for (int mt = 0; mt < 2; mt++) {
#pragma unroll
            for (int h = 0; h < 2; h++) {
                int r = wm * 32 + mt * 16 + qrow + h * 8;
#pragma unroll
                for (int nt = 0; nt < 8; nt++) {
                    sf[r * 129 + ocl + nt * 8] =
                        fminf(fmaxf(rintf(__fmul_rn(M, acc[mt][nt][h*2])),   lo), hi);
                    sf[r * 129 + ocl + nt * 8 + 1] =
                        fminf(fmaxf(rintf(__fmul_rn(M, acc[mt][nt][h*2+1])), lo), hi);
                }
            }
        }
        __syncthreads();
        // phase 2: coalesced residual qadd + NCHW write (lane <-> consecutive valid px)
        const float ra = __fdiv_rn(*ps_x,   *ps_add);
        const float rb = __fdiv_rn(*ps_out, *ps_add);
        const float za = *pz_add;
        const float zx = *pzx;
#pragma unroll 1
        for (int b4 = 0; b4 < 2; b4++) {
            int pl = b4 * 32 + lane;
            int vp = P0 + pl;
            int n  = vp / 784;
            int rr = vp - n * 784;
            int oh = rr / 28;
            int ow = rr - oh * 28;
            size_t base = (((size_t)n * CH + ocb) * HH + oh) * WW + ow;
#pragma unroll
            for (int i = 0; i < 32; i++) {
                int oc = wid * 32 + i;
                size_t a = base + (size_t)oc * 784;
                float xf = xin[a];
                float y  = __fadd_rn(__fmul_rn(ra, __fsub_rn(xf, zx)),
                                     __fmul_rn(rb, sf[pl * 129 + oc]));
                out[a] = fminf(fmaxf(rintf(y) + za, 0.f), 255.f);
            }
        }
    }
}

// ---------------- launch ----------------
extern "C" void kernel_launch(void* const* d_in, const int* in_sizes, int n_in,
                              void* d_out, int out_size) {
    const float* x    = (const float*)d_in[0];
    const float* w1   = (const float*)d_in[1];
    const float* w2   = (const float*)d_in[2];
    const float* s_x  = (const float*)d_in[3];
    const float* z_x  = (const float*)d_in[4];
    const float* s_w1 = (const float*)d_in[5];
    const float* s_c1 = (const float*)d_in[6];
    const float* z_c1 = (const float*)d_in[7];
    const float* s_w2 = (const float*)d_in[8];
    const float* s_c2 = (const float*)d_in[9];
    const float* z_c2 = (const float*)d_in[10];
    const float* s_ad = (const float*)d_in[11];
    const float* z_ad = (const float*)d_in[12];
    float* out = (float*)d_out;

    cudaFuncSetAttribute(k_conv<0>, cudaFuncAttributeMaxDynamicSharedMemorySize, SMEM_TOTAL);
    cudaFuncSetAttribute(k_conv<1>, cudaFuncAttributeMaxDynamicSharedMemorySize, SMEM_TOTAL);

    int zthreads = 2 * RING_SLOTS * 32;
    k_zero_halo<<<(zthreads + 255) / 256, 256>>>();
    k_pack_x<<<NB * HH, 256>>>(x, z_x);
    k_pack_w2<<<2 * 9 * 256, 256>>>(w1, w2);

    dim3 grid(NMT, 2);
    k_conv<0><<<grid, 128, SMEM_TOTAL>>>(s_x, s_w1, s_c1, z_c1,
                                         s_x, s_ad, z_ad, nullptr, z_x, nullptr);
    k_conv<1><<<grid, 128, SMEM_TOTAL>>>(s_c1, s_w2, s_c2, z_c2,
                                         s_x, s_ad, z_ad, x, z_x, out);
}

// round 17
// speedup vs baseline: 1.1969x; 1.0560x over previous
#include <cuda_runtime.h>
#include <cuda_bf16.h>
#include <stdint.h>

// ---------------- problem constants ----------------
#define NB   64
#define CH   256
#define HH   28
#define WW   28
#define HPX  900              // 30*30 padded pixels per image
#define NPIX (NB*HPX)         // 57600 padded
#define NVPX (NB*HH*WW)       // 50176 valid output pixels
#define NPIX_PAD 57728
#define MT   64               // valid pixels per CTA
#define NMT  (NVPX/MT)        // 784
#define NSTAGE 36             // 9 taps * 4 ic-chunks (64 ic)
#define NBUF 2
#define A_BYTES 8192          // 64 rows * 128B
#define B_BYTES 16384         // 128 rows * 128B
#define STAGE_BYTES (A_BYTES + B_BYTES)        // 24576
#define SMEM_TOTAL (NBUF*STAGE_BYTES)          // 49152 -> 4 CTAs/SM

// ---------------- device scratch ----------------
__device__ __align__(16) __nv_bfloat16 g_axs [(size_t)NPIX_PAD*CH];  // x - z_x, pad 0
__device__ __align__(16) __nv_bfloat16 g_amid[(size_t)NPIX_PAD*CH];  // mid - z_c1, pad 0
__device__ __align__(16) __nv_bfloat16 g_wb1[9*CH*CH];               // [tap][oc][ic]
__device__ __align__(16) __nv_bfloat16 g_wb2[9*CH*CH];

// ---------------- PTX helpers ----------------
__device__ __forceinline__ uint32_t smem_u32(const void* p) {
    uint32_t a;
    asm("{ .reg .u64 t; cvta.to.shared.u64 t, %1; cvt.u32.u64 %0, t; }" : "=r"(a) : "l"(p));
    return a;
}
__device__ __forceinline__ void cp16(uint32_t sdst, const void* gsrc) {
    asm volatile("cp.async.cg.shared.global [%0], [%1], 16;" :: "r"(sdst), "l"(gsrc));
}
#define CP_COMMIT() asm volatile("cp.async.commit_group;" ::: "memory")
template <int N> __device__ __forceinline__ void cp_wait() {
    asm volatile("cp.async.wait_group %0;" :: "n"(N) : "memory");
}
__device__ __forceinline__ void ldm4(uint32_t* r, uint32_t addr) {
    asm volatile("ldmatrix.sync.aligned.m8n8.x4.shared.b16 {%0,%1,%2,%3}, [%4];"
        : "=r"(r[0]), "=r"(r[1]), "=r"(r[2]), "=r"(r[3]) : "r"(addr));
}
__device__ __forceinline__ void mma_bf16(float* d, const uint32_t* a, const uint32_t* b) {
    asm volatile("mma.sync.aligned.m16n8k16.row.col.f32.bf16.bf16.f32 "
        "{%0,%1,%2,%3},{%4,%5,%6,%7},{%8,%9},{%0,%1,%2,%3};"
        : "+f"(d[0]), "+f"(d[1]), "+f"(d[2]), "+f"(d[3])
        : "r"(a[0]), "r"(a[1]), "r"(a[2]), "r"(a[3]), "r"(b[0]), "r"(b[1]));
}

// valid pixel -> padded pixel index of its CENTER
__device__ __forceinline__ int pad_idx(int vp) {
    int n  = vp / 784;
    int r  = vp - n * 784;
    int oh = r / 28;
    int ow = r - oh * 28;
    return n * HPX + (oh + 1) * 30 + ow + 1;
}

// ---------------- packing kernels ----------------
#define RING_SLOTS (64*116)
__global__ void k_zero_halo() {
    int idx = blockIdx.x * blockDim.x + threadIdx.x;
    int total = RING_SLOTS * 32;
    if (idx >= 2 * total) return;
    int arr = idx >= total;
    int t = arr ? idx - total : idx;
    int chunk = t & 31;
    int slot  = t >> 5;
    int img = slot / 116, i = slot % 116;
    int q;
    if (i < 30)       q = i;
    else if (i < 60)  q = 870 + (i - 30);
    else if (i < 88)  q = (i - 60 + 1) * 30;
    else              q = (i - 88 + 1) * 30 + 29;
    size_t P = (size_t)img * HPX + q;
    int4 z = make_int4(0, 0, 0, 0);
    if (arr == 0) ((int4*)(g_axs  + P * 256))[chunk] = z;
    else          ((int4*)(g_amid + P * 256))[chunk] = z;
}

__global__ void k_pack_x(const float* __restrict__ x, const float* __restrict__ pzx) {
    __shared__ __nv_bfloat16 s[28 * 258];
    int n  = blockIdx.x / 28;
    int oh = blockIdx.x % 28;
    float zx = *pzx;
    for (int i = threadIdx.x; i < 28 * 256; i += 256) {
        int c = i / 28, ow = i % 28;
        float g = x[(((size_t)n * CH + c) * HH + oh) * WW + ow];
        s[ow * 258 + c] = __float2bfloat16(__fsub_rn(g, zx));
    }
    __syncthreads();
    for (int i = threadIdx.x; i < 28 * 256; i += 256) {
        int ow = i >> 8, c = i & 255;
        g_axs[((size_t)n * HPX + (oh + 1) * 30 + ow + 1) * CH + c] = s[ow * 258 + c];
    }
}

__global__ void k_pack_w2(const float* __restrict__ w1, const float* __restrict__ w2) {
    int idx = blockIdx.x * blockDim.x + threadIdx.x;
    int which = idx >= 9*256*256;
    int j = which ? idx - 9*256*256 : idx;
    int ic  = j & 255;
    int oc  = (j >> 8) & 255;
    int tap = j >> 16;
    const float* w = which ? w2 : w1;
    __nv_bfloat16 v = __float2bfloat16(w[((size_t)oc * CH + ic) * 9 + tap]);
    if (which == 0) g_wb1[j] = v; else g_wb2[j] = v;
}

// ---------------- bf16 HMMA implicit-GEMM conv ----------------
// CTA: 64 valid px x 128 oc; 4 warps, warp tile 32x64; 4 CTAs/SM; grid 784x2.
// Double-buffered smem (NBUF=2): cp_wait<0> + barrier, then prefetch s+1 over compute s.
template <int MODE>
__global__ __launch_bounds__(128, 4) void k_conv(
    const float* __restrict__ ps_in,  const float* __restrict__ ps_w,
    const float* __restrict__ ps_out, const float* __restrict__ pz_out,
    const float* __restrict__ ps_x,   const float* __restrict__ ps_add,
    const float* __restrict__ pz_add,
    const float* __restrict__ xin,    const float* __restrict__ pzx,
    float* __restrict__ out)
{
    extern __shared__ char smem[];
    const uint32_t sb = smem_u32(smem);
    const __nv_bfloat16* act = (MODE == 0) ? g_axs : g_amid;
    const __nv_bfloat16* wq  = (MODE == 0) ? g_wb1 : g_wb2;

    const int tid  = threadIdx.x;
    const int lane = tid & 31;
    const int wid  = tid >> 5;
    const int wm   = wid & 1;           // 2 m-warps (32 px each)
    const int wn   = wid >> 1;          // 2 n-warps (64 oc each)
    const int P0   = blockIdx.x * MT;
    const int ocb  = blockIdx.y * 128;

    // A-row gather offsets: TOP-LEFT of each pixel's 3x3 window (= center - 31)
    uint32_t poff[4];
    {
        int row0 = tid >> 3;            // 0..15
#pragma unroll
        for (int i = 0; i < 4; i++)
            poff[i] = (uint32_t)(pad_idx(P0 + row0 + i * 16) - 31) * 512u;
    }
    const int c16 = tid & 7;

    float acc[2][8][4];
#pragma unroll
    for (int mt = 0; mt < 2; mt++)
#pragma unroll
        for (int nt = 0; nt < 8; nt++)
#pragma unroll
            for (int j = 0; j < 4; j++) acc[mt][nt][j] = 0.f;

    // stage loader: A 4 gathered rows + B 8 linear rows per thread
    auto load_stage = [&](int s) {
        int tap = s >> 2;
        int ic0 = (s & 3) * 64;
        int off = (tap / 3) * 30 + (tap % 3);
        uint32_t bufA = sb + (s % NBUF) * STAGE_BYTES;
        uint32_t bufB = bufA + A_BYTES;
        const char* gaB = (const char*)act + (size_t)off * 512 + ic0 * 2 + c16 * 16;
        const char* gb  = (const char*)wq + ((size_t)tap * 256 + ocb) * 512 + ic0 * 2;
        int row0 = tid >> 3;
        uint32_t swb = (uint32_t)(row0 * 128 + ((c16 ^ (row0 & 7)) << 4));
#pragma unroll
        for (int i = 0; i < 4; i++) {
            cp16(bufA + swb + i * 2048, gaB + poff[i]);
        }
#pragma unroll
        for (int i = 0; i < 8; i++) {
            int row = row0 + i * 16;
            uint32_t sw = (uint32_t)(row * 128 + ((c16 ^ (row & 7)) << 4));
            cp16(bufB + sw, gb + (size_t)row * 512 + c16 * 16);
        }
        CP_COMMIT();
    };

    load_stage(0);

    const int lrow = (lane & 7) + ((lane >> 3) & 1) * 8;
    const int lchk = lane >> 4;

#pragma unroll 1
    for (int s = 0; s < NSTAGE; s++) {
        cp_wait<0>();                    // stage s resident
        __syncthreads();                 // all warps done with buffer (s+1)%2

        uint32_t bufA = sb + (s % NBUF) * STAGE_BYTES;
        uint32_t bufB = bufA + A_BYTES;

        if (s + 1 < NSTAGE) load_stage(s + 1);   // overlaps compute of s

#pragma unroll
        for (int g = 0; g < 4; g++) {
            const int c = (g << 1) | lchk;
            uint32_t af[2][4];
#pragma unroll
            for (int mt = 0; mt < 2; mt++) {
                int r = wm * 32 + mt * 16 + lrow;
                ldm4(af[mt], bufA + r * 128 + ((c ^ (r & 7)) << 4));
            }
            uint32_t bf[8][2];
#pragma unroll
            for (int nt2 = 0; nt2 < 4; nt2++) {
                int r = wn * 64 + nt2 * 16 + lrow;
                uint32_t rr[4];
                ldm4(rr, bufB + r * 128 + ((c ^ (r & 7)) << 4));
                bf[nt2*2][0]   = rr[0]; bf[nt2*2][1]   = rr[2];
                bf[nt2*2+1][0] = rr[1]; bf[nt2*2+1][1] = rr[3];
            }
#pragma unroll
            for (int mt = 0; mt < 2; mt++)
#pragma unroll
                for (int nt = 0; nt < 8; nt++)
                    mma_bf16(acc[mt][nt], af[mt], bf[nt]);
        }
    }

    // ---------------- epilogue ----------------
    const float M  = __fdiv_rn(__fmul_rn(*ps_in, *ps_w), *ps_out);
    const float zo = *pz_out;
    const float lo = -zo, hi = 255.f - zo;     // clamp in shifted domain
    const int qrow = lane >> 2;
    const int cc   = (lane & 3) << 1;

    if (MODE == 0) {
        const int ocw = ocb + wn * 64;
#pragma unroll
        for (int mt = 0; mt < 2; mt++) {
#pragma unroll
            for (int h = 0; h < 2; h++) {
                int r  = wm * 32 + mt * 16 + qrow + h * 8;
                size_t base = (size_t)pad_idx(P0 + r) * 256 + ocw + cc;
#pragma unroll
                for (int nt = 0; nt < 8; nt++) {
                    float t0 = fminf(fmaxf(rintf(__fmul_rn(M, acc[mt][nt][h*2])),   lo), hi);
                    float t1 = fminf(fmaxf(rintf(__fmul_rn(M, acc[mt][nt][h*2+1])), lo), hi);
                    __nv_bfloat162 u;
                    u.x = __float2bfloat16(t0);
                    u.y = __float2bfloat16(t1);
                    *(__nv_bfloat162*)(g_amid + base + nt * 8) = u;
                }
            }
        }
    } else {
        // phase 1: requantized shifted conv2 value -> smem tile [64 px][128 oc] stride 129
        float* sf = (float*)smem;
        __syncthreads();                        // all warps done reading stage bufs
        const int ocl = wn * 64 + cc;
#pragma unroll
        for (int mt = 0; mt < 2; mt++) {
#pragma unroll
            for (int h = 0; h < 2; h++) {
                int r = wm * 32 + mt * 16 + qrow + h * 8;
#pragma unroll
                for (int nt = 0; nt < 8; nt++) {
                    sf[r * 129 + ocl + nt * 8] =
                        fminf(fmaxf(rintf(__fmul_rn(M, acc[mt][nt][h*2])),   lo), hi);
                    sf[r * 129 + ocl + nt * 8 + 1] =
                        fminf(fmaxf(rintf(__fmul_rn(M, acc[mt][nt][h*2+1])), lo), hi);
                }
            }
        }
        __syncthreads();
        // phase 2: coalesced residual qadd + NCHW write (lane <-> consecutive valid px)
        const float ra = __fdiv_rn(*ps_x,   *ps_add);
        const float rb = __fdiv_rn(*ps_out, *ps_add);
        const float za = *pz_add;
        const float zx = *pzx;
#pragma unroll 1
        for (int b4 = 0; b4 < 2; b4++) {
            int pl = b4 * 32 + lane;
            int vp = P0 + pl;
            int n  = vp / 784;
            int rr = vp - n * 784;
            int oh = rr / 28;
            int ow = rr - oh * 28;
            size_t base = (((size_t)n * CH + ocb) * HH + oh) * WW + ow;
#pragma unroll
            for (int i = 0; i < 32; i++) {
                int oc = wid * 32 + i;
                size_t a = base + (size_t)oc * 784;
                float xf = xin[a];
                float y  = __fadd_rn(__fmul_rn(ra, __fsub_rn(xf, zx)),
                                     __fmul_rn(rb, sf[pl * 129 + oc]));
                out[a] = fminf(fmaxf(rintf(y) + za, 0.f), 255.f);
            }
        }
    }
}

// ---------------- launch ----------------
extern "C" void kernel_launch(void* const* d_in, const int* in_sizes, int n_in,
                              void* d_out, int out_size) {
    const float* x    = (const float*)d_in[0];
    const float* w1   = (const float*)d_in[1];
    const float* w2   = (const float*)d_in[2];
    const float* s_x  = (const float*)d_in[3];
    const float* z_x  = (const float*)d_in[4];
    const float* s_w1 = (const float*)d_in[5];
    const float* s_c1 = (const float*)d_in[6];
    const float* z_c1 = (const float*)d_in[7];
    const float* s_w2 = (const float*)d_in[8];
    const float* s_c2 = (const float*)d_in[9];
    const float* z_c2 = (const float*)d_in[10];
    const float* s_ad = (const float*)d_in[11];
    const float* z_ad = (const float*)d_in[12];
    float* out = (float*)d_out;

    cudaFuncSetAttribute(k_conv<0>, cudaFuncAttributeMaxDynamicSharedMemorySize, SMEM_TOTAL);
    cudaFuncSetAttribute(k_conv<1>, cudaFuncAttributeMaxDynamicSharedMemorySize, SMEM_TOTAL);

    int zthreads = 2 * RING_SLOTS * 32;
    k_zero_halo<<<(zthreads + 255) / 256, 256>>>();
    k_pack_x<<<NB * HH, 256>>>(x, z_x);
    k_pack_w2<<<2 * 9 * 256, 256>>>(w1, w2);

    dim3 grid(NMT, 2);
    k_conv<0><<<grid, 128, SMEM_TOTAL>>>(s_x, s_w1, s_c1, z_c1,
                                         s_x, s_ad, z_ad, nullptr, z_x, nullptr);
    k_conv<1><<<grid, 128, SMEM_TOTAL>>>(s_c1, s_w2, s_c2, z_c2,
                                         s_x, s_ad, z_ad, x, z_x, out);
}